// round 1
// baseline (speedup 1.0000x reference)
#include <cuda_runtime.h>

namespace {
constexpr int B = 8, N = 1024, DIM = 512, H = 8, DH = 64, INNER = 512, G = B * H;
constexpr float SCALE = 0.125f;
}

// Scratch (device globals — allocation-free rule)
__device__ float g_q[(size_t)G * N * DH];
__device__ float g_k[(size_t)G * N * DH];
__device__ float g_v[(size_t)G * N * DH];
__device__ float g_S[(size_t)G * N * N];   // dots, then attn probs (reused)
__device__ float g_L[(size_t)G * N * N];   // lidar sim logits
__device__ float g_y[(size_t)B * N * INNER];

// ---------------------------------------------------------------------------
// K1: qkv = x @ w_qkv^T, scattered directly into head-major q/k/v buffers.
// 64x64 tile, BK=16, 256 threads, 4x4 per thread.
// ---------------------------------------------------------------------------
__global__ __launch_bounds__(256) void k_qkv(const float* __restrict__ x,
                                             const float* __restrict__ w) {
    __shared__ float As[16][64];
    __shared__ float Bs[16][64];
    const int t = threadIdx.x;
    const int tx = t & 15, ty = t >> 4;
    const int m0 = blockIdx.y * 64;
    const int c0 = blockIdx.x * 64;
    const int lr = t >> 2, lc = (t & 3) * 4;
    float acc[4][4] = {};
    for (int k0 = 0; k0 < DIM; k0 += 16) {
        float4 a = *(const float4*)&x[(size_t)(m0 + lr) * DIM + k0 + lc];
        float4 bv = *(const float4*)&w[(size_t)(c0 + lr) * DIM + k0 + lc];
        As[lc + 0][lr] = a.x;  As[lc + 1][lr] = a.y;
        As[lc + 2][lr] = a.z;  As[lc + 3][lr] = a.w;
        Bs[lc + 0][lr] = bv.x; Bs[lc + 1][lr] = bv.y;
        Bs[lc + 2][lr] = bv.z; Bs[lc + 3][lr] = bv.w;
        __syncthreads();
#pragma unroll
        for (int kk = 0; kk < 16; kk++) {
            float4 av = *(const float4*)&As[kk][ty * 4];
            float4 bb = *(const float4*)&Bs[kk][tx * 4];
            float aa[4] = {av.x, av.y, av.z, av.w};
            float bc[4] = {bb.x, bb.y, bb.z, bb.w};
#pragma unroll
            for (int i = 0; i < 4; i++)
#pragma unroll
                for (int j = 0; j < 4; j++) acc[i][j] += aa[i] * bc[j];
        }
        __syncthreads();
    }
    // c0 is a multiple of 64 -> whole tile lives in one (part, h)
    const int part = c0 >> 9;
    const int h = (c0 & 511) >> 6;
    float* dst = part == 0 ? g_q : (part == 1 ? g_k : g_v);
#pragma unroll
    for (int i = 0; i < 4; i++) {
        int m = m0 + ty * 4 + i;
        int b = m >> 10, n = m & 1023;
        float* row = dst + ((size_t)((b * H + h) * N + n)) * DH + tx * 4;
        float4 o = make_float4(acc[i][0], acc[i][1], acc[i][2], acc[i][3]);
        *(float4*)row = o;
    }
}

// ---------------------------------------------------------------------------
// K2: batched NT GEMM (K=64): S = scale * A @ B^T per head. LIDAR variant
// reads straight out of the interleaved [b,n,h*d] lidar tensor.
// ---------------------------------------------------------------------------
template <bool LIDAR>
__global__ __launch_bounds__(256) void k_scores(const float* __restrict__ lidar) {
    __shared__ float As[16][64];
    __shared__ float Bs[16][64];
    const int t = threadIdx.x;
    const int tx = t & 15, ty = t >> 4;
    const int g = blockIdx.z;
    const int b = g >> 3, h = g & 7;
    const int i0 = blockIdx.y * 64, j0 = blockIdx.x * 64;
    const int lr = t >> 2, lc = (t & 3) * 4;
    const float* Abase;
    const float* Bbase;
    int stride;
    if (LIDAR) {
        Abase = lidar + (size_t)b * N * INNER + h * DH;
        Bbase = Abase;
        stride = INNER;
    } else {
        Abase = g_q + (size_t)g * N * DH;
        Bbase = g_k + (size_t)g * N * DH;
        stride = DH;
    }
    float acc[4][4] = {};
#pragma unroll
    for (int k0 = 0; k0 < DH; k0 += 16) {
        float4 a = *(const float4*)&Abase[(size_t)(i0 + lr) * stride + k0 + lc];
        float4 bv = *(const float4*)&Bbase[(size_t)(j0 + lr) * stride + k0 + lc];
        As[lc + 0][lr] = a.x;  As[lc + 1][lr] = a.y;
        As[lc + 2][lr] = a.z;  As[lc + 3][lr] = a.w;
        Bs[lc + 0][lr] = bv.x; Bs[lc + 1][lr] = bv.y;
        Bs[lc + 2][lr] = bv.z; Bs[lc + 3][lr] = bv.w;
        __syncthreads();
#pragma unroll
        for (int kk = 0; kk < 16; kk++) {
            float4 av = *(const float4*)&As[kk][ty * 4];
            float4 bb = *(const float4*)&Bs[kk][tx * 4];
            float aa[4] = {av.x, av.y, av.z, av.w};
            float bc[4] = {bb.x, bb.y, bb.z, bb.w};
#pragma unroll
            for (int i = 0; i < 4; i++)
#pragma unroll
                for (int j = 0; j < 4; j++) acc[i][j] += aa[i] * bc[j];
        }
        __syncthreads();
    }
    float* out = (LIDAR ? g_L : g_S) + (size_t)g * N * N;
#pragma unroll
    for (int i = 0; i < 4; i++) {
        float4 o = make_float4(acc[i][0] * SCALE, acc[i][1] * SCALE,
                               acc[i][2] * SCALE, acc[i][3] * SCALE);
        *(float4*)&out[(size_t)(i0 + ty * 4 + i) * N + j0 + tx * 4] = o;
    }
}

// ---------------------------------------------------------------------------
// K3 (fused): per row: p_l = softmax(L); mid = c0*S + c1*p_l + cb;
//             S <- softmax(mid).  One block per (g, i) row, 4 elems/thread.
// ---------------------------------------------------------------------------
__global__ __launch_bounds__(256) void k_blend(const float* __restrict__ conv_w,
                                               const float* __restrict__ conv_b) {
    const size_t base = (size_t)blockIdx.x * N;
    const int t = threadIdx.x;
    __shared__ float redA[8];
    __shared__ float redB[8];

    float4 lv = *(const float4*)&g_L[base + t * 4];
    // --- lidar softmax stats ---
    float m = fmaxf(fmaxf(lv.x, lv.y), fmaxf(lv.z, lv.w));
    for (int o = 16; o; o >>= 1) m = fmaxf(m, __shfl_xor_sync(0xffffffffu, m, o));
    if ((t & 31) == 0) redA[t >> 5] = m;
    __syncthreads();
    m = redA[0];
#pragma unroll
    for (int w = 1; w < 8; w++) m = fmaxf(m, redA[w]);
    float e0 = __expf(lv.x - m), e1 = __expf(lv.y - m);
    float e2 = __expf(lv.z - m), e3 = __expf(lv.w - m);
    float s = e0 + e1 + e2 + e3;
    for (int o = 16; o; o >>= 1) s += __shfl_xor_sync(0xffffffffu, s, o);
    if ((t & 31) == 0) redB[t >> 5] = s;
    __syncthreads();
    s = redB[0];
#pragma unroll
    for (int w = 1; w < 8; w++) s += redB[w];
    const float inv = 1.0f / s;

    // --- blend ---
    float4 sv = *(const float4*)&g_S[base + t * 4];
    const float c0 = conv_w[0], c1 = conv_w[1], cb = conv_b[0];
    float m0 = c0 * sv.x + c1 * e0 * inv + cb;
    float m1 = c0 * sv.y + c1 * e1 * inv + cb;
    float m2 = c0 * sv.z + c1 * e2 * inv + cb;
    float m3 = c0 * sv.w + c1 * e3 * inv + cb;

    // --- mid softmax ---
    float mm = fmaxf(fmaxf(m0, m1), fmaxf(m2, m3));
    for (int o = 16; o; o >>= 1) mm = fmaxf(mm, __shfl_xor_sync(0xffffffffu, mm, o));
    __syncthreads();
    if ((t & 31) == 0) redA[t >> 5] = mm;
    __syncthreads();
    mm = redA[0];
#pragma unroll
    for (int w = 1; w < 8; w++) mm = fmaxf(mm, redA[w]);
    float p0 = __expf(m0 - mm), p1 = __expf(m1 - mm);
    float p2 = __expf(m2 - mm), p3 = __expf(m3 - mm);
    float z = p0 + p1 + p2 + p3;
    for (int o = 16; o; o >>= 1) z += __shfl_xor_sync(0xffffffffu, z, o);
    __syncthreads();
    if ((t & 31) == 0) redB[t >> 5] = z;
    __syncthreads();
    z = redB[0];
#pragma unroll
    for (int w = 1; w < 8; w++) z += redB[w];
    const float invz = 1.0f / z;
    float4 o4 = make_float4(p0 * invz, p1 * invz, p2 * invz, p3 * invz);
    *(float4*)&g_S[base + t * 4] = o4;
}

// ---------------------------------------------------------------------------
// K4: O1 = attn @ V (per head, K=1024) fused with per-head merge:
//     y = O1 @ w_merge^T + b_merge, scattered to [b, n, h*64+d'] layout.
// ---------------------------------------------------------------------------
__global__ __launch_bounds__(256) void k_av_merge(const float* __restrict__ w_merge,
                                                  const float* __restrict__ b_merge) {
    __shared__ float As[16][64];
    __shared__ float Bs[16][64];
    __shared__ float Os[64][64];
    __shared__ float WmT[64][64];   // WmT[d][d'] = w_merge[d'][d]
    __shared__ float bm[64];
    const int t = threadIdx.x;
    const int tx = t & 15, ty = t >> 4;
    const int g = blockIdx.z;
    const int b = g >> 3, h = g & 7;
    const int i0 = blockIdx.y * 64;

    // stage merge weights (transposed) + bias
    {
        int r = t >> 2, c4 = (t & 3) * 4;        // covers 64x16 per pass
        for (int cc = 0; cc < 64; cc += 16) {
            float4 wv = *(const float4*)&w_merge[(size_t)r * DH + cc + c4];
            WmT[cc + c4 + 0][r] = wv.x;
            WmT[cc + c4 + 1][r] = wv.y;
            WmT[cc + c4 + 2][r] = wv.z;
            WmT[cc + c4 + 3][r] = wv.w;
        }
        if (t < 64) bm[t] = b_merge[t];
    }

    const float* P = g_S + (size_t)g * N * N;
    const float* V = g_v + (size_t)g * N * DH;
    const int lrA = t >> 2, lcA = (t & 3) * 4;
    const int kkB = t >> 4, dB = (t & 15) * 4;
    float acc[4][4] = {};
    for (int k0 = 0; k0 < N; k0 += 16) {
        float4 a = *(const float4*)&P[(size_t)(i0 + lrA) * N + k0 + lcA];
        float4 vv = *(const float4*)&V[(size_t)(k0 + kkB) * DH + dB];
        As[lcA + 0][lrA] = a.x; As[lcA + 1][lrA] = a.y;
        As[lcA + 2][lrA] = a.z; As[lcA + 3][lrA] = a.w;
        *(float4*)&Bs[kkB][dB] = vv;
        __syncthreads();
#pragma unroll
        for (int kk = 0; kk < 16; kk++) {
            float4 av = *(const float4*)&As[kk][ty * 4];
            float4 bb = *(const float4*)&Bs[kk][tx * 4];
            float aa[4] = {av.x, av.y, av.z, av.w};
            float bc[4] = {bb.x, bb.y, bb.z, bb.w};
#pragma unroll
            for (int i = 0; i < 4; i++)
#pragma unroll
                for (int j = 0; j < 4; j++) acc[i][j] += aa[i] * bc[j];
        }
        __syncthreads();
    }
    // park O1 tile in smem
#pragma unroll
    for (int i = 0; i < 4; i++)
        *(float4*)&Os[ty * 4 + i][tx * 4] =
            make_float4(acc[i][0], acc[i][1], acc[i][2], acc[i][3]);
    __syncthreads();

    // merge: out[i][d'] = bm[d'] + sum_d Os[i][d] * WmT[d][d']
    float acc2[4][4];
#pragma unroll
    for (int i = 0; i < 4; i++)
#pragma unroll
        for (int j = 0; j < 4; j++) acc2[i][j] = bm[tx * 4 + j];
#pragma unroll 8
    for (int d = 0; d < 64; d++) {
        float4 wv = *(const float4*)&WmT[d][tx * 4];
        float wc[4] = {wv.x, wv.y, wv.z, wv.w};
#pragma unroll
        for (int i = 0; i < 4; i++) {
            float ov = Os[ty * 4 + i][d];
#pragma unroll
            for (int j = 0; j < 4; j++) acc2[i][j] += ov * wc[j];
        }
    }
#pragma unroll
    for (int i = 0; i < 4; i++) {
        int n = i0 + ty * 4 + i;
        float* dst = g_y + (size_t)(b * N + n) * INNER + h * DH + tx * 4;
        *(float4*)dst = make_float4(acc2[i][0], acc2[i][1], acc2[i][2], acc2[i][3]);
    }
}

// ---------------------------------------------------------------------------
// K5: out = y @ w_out^T + b_out
// ---------------------------------------------------------------------------
__global__ __launch_bounds__(256) void k_out(const float* __restrict__ w,
                                             const float* __restrict__ bias,
                                             float* __restrict__ out) {
    __shared__ float As[16][64];
    __shared__ float Bs[16][64];
    const int t = threadIdx.x;
    const int tx = t & 15, ty = t >> 4;
    const int m0 = blockIdx.y * 64;
    const int c0 = blockIdx.x * 64;
    const int lr = t >> 2, lc = (t & 3) * 4;
    float acc[4][4] = {};
    for (int k0 = 0; k0 < INNER; k0 += 16) {
        float4 a = *(const float4*)&g_y[(size_t)(m0 + lr) * INNER + k0 + lc];
        float4 bv = *(const float4*)&w[(size_t)(c0 + lr) * INNER + k0 + lc];
        As[lc + 0][lr] = a.x;  As[lc + 1][lr] = a.y;
        As[lc + 2][lr] = a.z;  As[lc + 3][lr] = a.w;
        Bs[lc + 0][lr] = bv.x; Bs[lc + 1][lr] = bv.y;
        Bs[lc + 2][lr] = bv.z; Bs[lc + 3][lr] = bv.w;
        __syncthreads();
#pragma unroll
        for (int kk = 0; kk < 16; kk++) {
            float4 av = *(const float4*)&As[kk][ty * 4];
            float4 bb = *(const float4*)&Bs[kk][tx * 4];
            float aa[4] = {av.x, av.y, av.z, av.w};
            float bc[4] = {bb.x, bb.y, bb.z, bb.w};
#pragma unroll
            for (int i = 0; i < 4; i++)
#pragma unroll
                for (int j = 0; j < 4; j++) acc[i][j] += aa[i] * bc[j];
        }
        __syncthreads();
    }
#pragma unroll
    for (int i = 0; i < 4; i++) {
        int m = m0 + ty * 4 + i;
        int c = c0 + tx * 4;
        float4 o = make_float4(acc[i][0] + bias[c + 0], acc[i][1] + bias[c + 1],
                               acc[i][2] + bias[c + 2], acc[i][3] + bias[c + 3]);
        *(float4*)&out[(size_t)m * DIM + c] = o;
    }
}

__global__ __launch_bounds__(256) void k_copy(const float* __restrict__ src,
                                              float* __restrict__ dst, int n4) {
    int i = blockIdx.x * blockDim.x + threadIdx.x;
    if (i < n4) ((float4*)dst)[i] = ((const float4*)src)[i];
}

extern "C" void kernel_launch(void* const* d_in, const int* in_sizes, int n_in,
                              void* d_out, int out_size) {
    const float* x       = (const float*)d_in[0];
    const float* lidar   = (const float*)d_in[1];
    const float* w_qkv   = (const float*)d_in[2];
    const float* w_merge = (const float*)d_in[3];
    const float* b_merge = (const float*)d_in[4];
    const float* w_out   = (const float*)d_in[5];
    const float* b_out   = (const float*)d_in[6];
    const float* conv_w  = (const float*)d_in[7];
    const float* conv_b  = (const float*)d_in[8];
    float* out = (float*)d_out;

    k_qkv<<<dim3(24, 128), 256>>>(x, w_qkv);                 // qkv projection
    k_scores<false><<<dim3(16, 16, G), 256>>>(lidar);        // dots
    k_scores<true><<<dim3(16, 16, G), 256>>>(lidar);         // lidar sim
    k_blend<<<G * N, 256>>>(conv_w, conv_b);                 // fused double softmax
    k_av_merge<<<dim3(1, 16, G), 256>>>(w_merge, b_merge);   // attn@V + merge
    k_out<<<dim3(8, 128), 256>>>(w_out, b_out, out);         // out projection

    const int outElems = B * N * DIM;
    if (out_size >= 2 * outElems) {
        k_copy<<<(outElems / 4 + 255) / 256, 256>>>(lidar, out + outElems,
                                                    outElems / 4);
    }
}

// round 3
// speedup vs baseline: 2.1185x; 2.1185x over previous
#include <cuda_runtime.h>

namespace {
constexpr int B_ = 8, N_ = 1024, DIM = 512, H_ = 8, DH = 64, INNER = 512, G = 64;
constexpr float SCALE = 0.125f;
}

// Scratch (device globals — allocation-free rule)
__device__ float g_q[(size_t)G * N_ * DH];
__device__ float g_k[(size_t)G * N_ * DH];
__device__ float g_v[(size_t)G * N_ * DH];
__device__ float g_mid[(size_t)G * N_ * N_];
__device__ float g_y[(size_t)B_ * N_ * INNER];
__device__ float g_ml[G * N_];
__device__ float g_isl[G * N_];
__device__ float g_m2[G * N_];
__device__ float g_is2[G * N_];
__device__ float g_w2[DIM * INNER];
__device__ float g_b2[DIM];

// ---------------------------------------------------------------------------
// tf32 helpers
// ---------------------------------------------------------------------------
__device__ __forceinline__ float cvt_tf32f(float x) {
    unsigned r;
    asm("cvt.rna.tf32.f32 %0, %1;" : "=r"(r) : "f"(x));
    return __uint_as_float(r);
}

__device__ __forceinline__ void mma8(float* d, const unsigned* a, const unsigned* b) {
    asm("mma.sync.aligned.m16n8k8.row.col.f32.tf32.tf32.f32 "
        "{%0,%1,%2,%3}, {%4,%5,%6,%7}, {%8,%9}, {%0,%1,%2,%3};"
        : "+f"(d[0]), "+f"(d[1]), "+f"(d[2]), "+f"(d[3])
        : "r"(a[0]), "r"(a[1]), "r"(a[2]), "r"(a[3]), "r"(b[0]), "r"(b[1]));
}

// One BK=32 slab of mma over smem tiles.
// A: [BM][36] row-major along K.  B: n-major [BN][BSTR] (BKMAJ=false)
// or k-major [32][BSTR] (BKMAJ=true).
template <int MT, int NT, int WARPS_N, bool BKMAJ, int ASTR, int BSTR>
__device__ __forceinline__ void mma_slab(const float* As, const float* Bs,
                                         int warp, int g8, int t4,
                                         float (&acc)[MT][NT][4]) {
    const int wm = warp / WARPS_N, wn = warp % WARPS_N;
#pragma unroll
    for (int ks = 0; ks < 4; ks++) {
        const int c = ks * 8 + t4;
        unsigned af[MT][4], bf[NT][2];
#pragma unroll
        for (int mt = 0; mt < MT; mt++) {
            int r = wm * (MT * 16) + mt * 16 + g8;
            af[mt][0] = __float_as_uint(As[r * ASTR + c]);
            af[mt][1] = __float_as_uint(As[(r + 8) * ASTR + c]);
            af[mt][2] = __float_as_uint(As[r * ASTR + c + 4]);
            af[mt][3] = __float_as_uint(As[(r + 8) * ASTR + c + 4]);
        }
#pragma unroll
        for (int nt = 0; nt < NT; nt++) {
            int n = wn * (NT * 8) + nt * 8 + g8;
            if constexpr (BKMAJ) {
                bf[nt][0] = __float_as_uint(Bs[c * BSTR + n]);
                bf[nt][1] = __float_as_uint(Bs[(c + 4) * BSTR + n]);
            } else {
                bf[nt][0] = __float_as_uint(Bs[n * BSTR + c]);
                bf[nt][1] = __float_as_uint(Bs[n * BSTR + c + 4]);
            }
        }
#pragma unroll
        for (int mt = 0; mt < MT; mt++)
#pragma unroll
            for (int nt = 0; nt < NT; nt++)
                mma8(acc[mt][nt], af[mt], bf[nt]);
    }
}

// 128 rows x 32 cols gmem -> smem (stride 36), tf32-converted, optional scale.
__device__ __forceinline__ void load_tile_128x32(float* S, const float* gsrc,
                                                 int ldg, float scale) {
    const int t = threadIdx.x;
    const int r = t >> 3, c4 = (t & 7) * 4;
#pragma unroll
    for (int p = 0; p < 4; p++) {
        float4 v = *(const float4*)(gsrc + (size_t)(r + p * 32) * ldg + c4);
        float4 o;
        o.x = cvt_tf32f(v.x * scale);
        o.y = cvt_tf32f(v.y * scale);
        o.z = cvt_tf32f(v.z * scale);
        o.w = cvt_tf32f(v.w * scale);
        *(float4*)(S + (r + p * 32) * 36 + c4) = o;
    }
}

// ---------------------------------------------------------------------------
// K1: qkv = x @ w_qkv^T  (M=8192, N=1536, K=512) -> head-major q/k/v
// ---------------------------------------------------------------------------
__global__ __launch_bounds__(256) void k_qkv(const float* __restrict__ x,
                                             const float* __restrict__ w) {
    __shared__ float As[128 * 36], Bs[128 * 36];
    const int t = threadIdx.x, warp = t >> 5, lane = t & 31;
    const int g8 = lane >> 2, t4 = lane & 3;
    const int n0 = blockIdx.x * 128, m0 = blockIdx.y * 128;
    float acc[4][4][4] = {};
    for (int k0 = 0; k0 < DIM; k0 += 32) {
        __syncthreads();
        load_tile_128x32(As, x + (size_t)m0 * DIM + k0, DIM, 1.f);
        load_tile_128x32(Bs, w + (size_t)n0 * DIM + k0, DIM, 1.f);
        __syncthreads();
        mma_slab<4, 4, 4, false, 36, 36>(As, Bs, warp, g8, t4, acc);
    }
    const int wm = warp >> 2, wn = warp & 3;
#pragma unroll
    for (int mt = 0; mt < 4; mt++)
#pragma unroll
        for (int nt = 0; nt < 4; nt++) {
            int col = n0 + wn * 32 + nt * 8 + 2 * t4;
            int part = col >> 9, h = (col >> 6) & 7, d = col & 63;
            float* dst = part == 0 ? g_q : (part == 1 ? g_k : g_v);
#pragma unroll
            for (int half = 0; half < 2; half++) {
                int row = m0 + wm * 64 + mt * 16 + g8 + half * 8;
                int b = row >> 10, n = row & 1023;
                float2 val = half ? make_float2(acc[mt][nt][2], acc[mt][nt][3])
                                  : make_float2(acc[mt][nt][0], acc[mt][nt][1]);
                *(float2*)&dst[((size_t)((b * 8 + h) * 1024 + n)) * 64 + d] = val;
            }
        }
}

// ---------------------------------------------------------------------------
// K2: lidar softmax row stats (online, nothing materialized).
// ---------------------------------------------------------------------------
__global__ __launch_bounds__(256) void k_lstats(const float* __restrict__ lidar) {
    __shared__ float As[128 * 36], Bs[128 * 36];
    __shared__ float red[4][128], bcast[128], mrun[128], srun[128];
    const int t = threadIdx.x, warp = t >> 5, lane = t & 31;
    const int g8 = lane >> 2, t4 = lane & 3;
    const int gidx = blockIdx.y, b = gidx >> 3, h = gidx & 7;
    const int i0 = blockIdx.x * 128;
    const float* base = lidar + (size_t)b * N_ * INNER + h * 64;
    const int wm = warp >> 2, wn = warp & 3;
    if (t < 128) { mrun[t] = -1e30f; srun[t] = 0.f; }
    for (int jt = 0; jt < 8; jt++) {
        float acc[4][4][4] = {};
#pragma unroll
        for (int k0 = 0; k0 < 64; k0 += 32) {
            __syncthreads();
            load_tile_128x32(As, base + (size_t)i0 * INNER + k0, INNER, SCALE);
            load_tile_128x32(Bs, base + (size_t)(jt * 128) * INNER + k0, INNER, 1.f);
            __syncthreads();
            mma_slab<4, 4, 4, false, 36, 36>(As, Bs, warp, g8, t4, acc);
        }
        // per-thread row maxes -> quad shuffle -> cross-warp via smem
        float vm[4][2];
#pragma unroll
        for (int mt = 0; mt < 4; mt++) {
            float a0 = -1e30f, a1 = -1e30f;
#pragma unroll
            for (int nt = 0; nt < 4; nt++) {
                a0 = fmaxf(a0, fmaxf(acc[mt][nt][0], acc[mt][nt][1]));
                a1 = fmaxf(a1, fmaxf(acc[mt][nt][2], acc[mt][nt][3]));
            }
#pragma unroll
            for (int off = 1; off <= 2; off <<= 1) {
                a0 = fmaxf(a0, __shfl_xor_sync(~0u, a0, off));
                a1 = fmaxf(a1, __shfl_xor_sync(~0u, a1, off));
            }
            vm[mt][0] = a0; vm[mt][1] = a1;
        }
        if (t4 == 0)
#pragma unroll
            for (int mt = 0; mt < 4; mt++) {
                red[wn][wm * 64 + mt * 16 + g8] = vm[mt][0];
                red[wn][wm * 64 + mt * 16 + g8 + 8] = vm[mt][1];
            }
        __syncthreads();
        if (t < 128) {
            float tm = fmaxf(fmaxf(red[0][t], red[1][t]), fmaxf(red[2][t], red[3][t]));
            bcast[t] = fmaxf(mrun[t], tm);
        }
        __syncthreads();
        float vs[4][2];
#pragma unroll
        for (int mt = 0; mt < 4; mt++) {
            int r = wm * 64 + mt * 16 + g8;
            float mn0 = bcast[r], mn1 = bcast[r + 8];
            float s0 = 0.f, s1 = 0.f;
#pragma unroll
            for (int nt = 0; nt < 4; nt++) {
                s0 += __expf(acc[mt][nt][0] - mn0) + __expf(acc[mt][nt][1] - mn0);
                s1 += __expf(acc[mt][nt][2] - mn1) + __expf(acc[mt][nt][3] - mn1);
            }
#pragma unroll
            for (int off = 1; off <= 2; off <<= 1) {
                s0 += __shfl_xor_sync(~0u, s0, off);
                s1 += __shfl_xor_sync(~0u, s1, off);
            }
            vs[mt][0] = s0; vs[mt][1] = s1;
        }
        __syncthreads();
        if (t4 == 0)
#pragma unroll
            for (int mt = 0; mt < 4; mt++) {
                red[wn][wm * 64 + mt * 16 + g8] = vs[mt][0];
                red[wn][wm * 64 + mt * 16 + g8 + 8] = vs[mt][1];
            }
        __syncthreads();
        if (t < 128) {
            float ts = red[0][t] + red[1][t] + red[2][t] + red[3][t];
            float mn = bcast[t];
            srun[t] = srun[t] * __expf(mrun[t] - mn) + ts;
            mrun[t] = mn;
        }
    }
    __syncthreads();
    if (t < 128) {
        g_ml[gidx * N_ + i0 + t] = mrun[t];
        g_isl[gidx * N_ + i0 + t] = 1.0f / srun[t];
    }
}

// ---------------------------------------------------------------------------
// K3: mid = c0*SCALE*(q k^T) + c1*softmax_row(SCALE*lid lid^T)   (conv_b dropped)
// ---------------------------------------------------------------------------
__global__ __launch_bounds__(256) void k_mid(const float* __restrict__ lidar,
                                             const float* __restrict__ conv_w) {
    __shared__ float As[128 * 36], Bs[128 * 36];
    __shared__ float mls[128], isls[128];
    const int t = threadIdx.x, warp = t >> 5, lane = t & 31;
    const int g8 = lane >> 2, t4 = lane & 3;
    const int gidx = blockIdx.z, b = gidx >> 3, h = gidx & 7;
    const int i0 = blockIdx.y * 128, j0 = blockIdx.x * 128;
    const float c0 = conv_w[0], c1 = conv_w[1];
    if (t < 128) {
        mls[t] = g_ml[gidx * N_ + i0 + t];
        isls[t] = g_isl[gidx * N_ + i0 + t];
    }
    const float* lbase = lidar + (size_t)b * N_ * INNER + h * 64;
    float acc[4][4][4] = {};
#pragma unroll
    for (int k0 = 0; k0 < 64; k0 += 32) {
        __syncthreads();
        load_tile_128x32(As, lbase + (size_t)i0 * INNER + k0, INNER, SCALE);
        load_tile_128x32(Bs, lbase + (size_t)j0 * INNER + k0, INNER, 1.f);
        __syncthreads();
        mma_slab<4, 4, 4, false, 36, 36>(As, Bs, warp, g8, t4, acc);
    }
    const int wm = warp >> 2, wn = warp & 3;
#pragma unroll
    for (int mt = 0; mt < 4; mt++) {
        int r = wm * 64 + mt * 16 + g8;
        float m0v = mls[r], i0v = isls[r] * c1;
        float m1v = mls[r + 8], i1v = isls[r + 8] * c1;
#pragma unroll
        for (int nt = 0; nt < 4; nt++) {
            acc[mt][nt][0] = i0v * __expf(acc[mt][nt][0] - m0v);
            acc[mt][nt][1] = i0v * __expf(acc[mt][nt][1] - m0v);
            acc[mt][nt][2] = i1v * __expf(acc[mt][nt][2] - m1v);
            acc[mt][nt][3] = i1v * __expf(acc[mt][nt][3] - m1v);
        }
    }
    const float* qb = g_q + (size_t)gidx * N_ * DH;
    const float* kb = g_k + (size_t)gidx * N_ * DH;
#pragma unroll
    for (int k0 = 0; k0 < 64; k0 += 32) {
        __syncthreads();
        load_tile_128x32(As, qb + (size_t)i0 * DH + k0, DH, c0 * SCALE);
        load_tile_128x32(Bs, kb + (size_t)j0 * DH + k0, DH, 1.f);
        __syncthreads();
        mma_slab<4, 4, 4, false, 36, 36>(As, Bs, warp, g8, t4, acc);
    }
    float* mid = g_mid + (size_t)gidx * N_ * N_;
#pragma unroll
    for (int mt = 0; mt < 4; mt++)
#pragma unroll
        for (int nt = 0; nt < 4; nt++) {
            int col = j0 + wn * 32 + nt * 8 + 2 * t4;
            int r = i0 + wm * 64 + mt * 16 + g8;
            *(float2*)&mid[(size_t)r * N_ + col] =
                make_float2(acc[mt][nt][0], acc[mt][nt][1]);
            *(float2*)&mid[(size_t)(r + 8) * N_ + col] =
                make_float2(acc[mt][nt][2], acc[mt][nt][3]);
        }
}

// ---------------------------------------------------------------------------
// K4: per-row max & expsum of mid.
// ---------------------------------------------------------------------------
__global__ __launch_bounds__(256) void k_midstats() {
    const size_t base = (size_t)blockIdx.x * N_;
    const int t = threadIdx.x;
    __shared__ float red[8];
    float4 v = *(const float4*)&g_mid[base + t * 4];
    float m = fmaxf(fmaxf(v.x, v.y), fmaxf(v.z, v.w));
    for (int o = 16; o; o >>= 1) m = fmaxf(m, __shfl_xor_sync(~0u, m, o));
    if ((t & 31) == 0) red[t >> 5] = m;
    __syncthreads();
    m = red[0];
#pragma unroll
    for (int w = 1; w < 8; w++) m = fmaxf(m, red[w]);
    float s = __expf(v.x - m) + __expf(v.y - m) + __expf(v.z - m) + __expf(v.w - m);
    for (int o = 16; o; o >>= 1) s += __shfl_xor_sync(~0u, s, o);
    __syncthreads();
    if ((t & 31) == 0) red[t >> 5] = s;
    __syncthreads();
    s = red[0];
#pragma unroll
    for (int w = 1; w < 8; w++) s += red[w];
    if (t == 0) { g_m2[blockIdx.x] = m; g_is2[blockIdx.x] = 1.0f / s; }
}

// ---------------------------------------------------------------------------
// K5: O1 = softmax(mid) @ V  (probs computed on the fly), written to g_y.
// BM=128, BN=64, warps 4x2, warp tile 32x32.
// ---------------------------------------------------------------------------
__global__ __launch_bounds__(256) void k_pv() {
    __shared__ float As[128 * 36], Bsv[32 * 72];
    __shared__ float m2s[128], is2s[128];
    const int t = threadIdx.x, warp = t >> 5, lane = t & 31;
    const int g8 = lane >> 2, t4 = lane & 3;
    const int gidx = blockIdx.y, i0 = blockIdx.x * 128;
    const int b = gidx >> 3, h = gidx & 7;
    if (t < 128) {
        m2s[t] = g_m2[gidx * N_ + i0 + t];
        is2s[t] = g_is2[gidx * N_ + i0 + t];
    }
    const float* midb = g_mid + (size_t)gidx * N_ * N_ + (size_t)i0 * N_;
    const float* vb = g_v + (size_t)gidx * N_ * DH;
    float acc[2][4][4] = {};
    for (int k0 = 0; k0 < N_; k0 += 32) {
        __syncthreads();
        {   // A: 128x32 probs
            int r = t >> 3, c4 = (t & 7) * 4;
#pragma unroll
            for (int p = 0; p < 4; p++) {
                int row = r + p * 32;
                float4 v = *(const float4*)(midb + (size_t)row * N_ + k0 + c4);
                float mm = m2s[row], ii = is2s[row];
                float4 o;
                o.x = cvt_tf32f(__expf(v.x - mm) * ii);
                o.y = cvt_tf32f(__expf(v.y - mm) * ii);
                o.z = cvt_tf32f(__expf(v.z - mm) * ii);
                o.w = cvt_tf32f(__expf(v.w - mm) * ii);
                *(float4*)(As + row * 36 + c4) = o;
            }
        }
        {   // B: V k-major 32x64, stride 72
            int j = t >> 4, d4 = (t & 15) * 4;
#pragma unroll
            for (int p = 0; p < 2; p++) {
                int jj = j + p * 16;
                float4 v = *(const float4*)(vb + (size_t)(k0 + jj) * DH + d4);
                float4 o;
                o.x = cvt_tf32f(v.x); o.y = cvt_tf32f(v.y);
                o.z = cvt_tf32f(v.z); o.w = cvt_tf32f(v.w);
                *(float4*)(Bsv + jj * 72 + d4) = o;
            }
        }
        __syncthreads();
        mma_slab<2, 4, 2, true, 36, 72>(As, Bsv, warp, g8, t4, acc);
    }
    const int wm = warp >> 1, wn = warp & 1;
    float* yb = g_y + (size_t)b * N_ * INNER + h * 64;
#pragma unroll
    for (int mt = 0; mt < 2; mt++)
#pragma unroll
        for (int nt = 0; nt < 4; nt++) {
            int d = wn * 32 + nt * 8 + 2 * t4;
            int n = i0 + wm * 32 + mt * 16 + g8;
            *(float2*)&yb[(size_t)n * INNER + d] =
                make_float2(acc[mt][nt][0], acc[mt][nt][1]);
            *(float2*)&yb[(size_t)(n + 8) * INNER + d] =
                make_float2(acc[mt][nt][2], acc[mt][nt][3]);
        }
}

// ---------------------------------------------------------------------------
// K6: out = y @ W2^T + bias2   (merge folded into W2)
// ---------------------------------------------------------------------------
__global__ __launch_bounds__(256) void k_out(float* __restrict__ out) {
    __shared__ float As[128 * 36], Bs[128 * 36];
    const int t = threadIdx.x, warp = t >> 5, lane = t & 31;
    const int g8 = lane >> 2, t4 = lane & 3;
    const int n0 = blockIdx.x * 128, m0 = blockIdx.y * 128;
    float acc[4][4][4] = {};
    for (int k0 = 0; k0 < INNER; k0 += 32) {
        __syncthreads();
        load_tile_128x32(As, g_y + (size_t)m0 * INNER + k0, INNER, 1.f);
        load_tile_128x32(Bs, g_w2 + (size_t)n0 * INNER + k0, INNER, 1.f);
        __syncthreads();
        mma_slab<4, 4, 4, false, 36, 36>(As, Bs, warp, g8, t4, acc);
    }
    const int wm = warp >> 2, wn = warp & 3;
#pragma unroll
    for (int mt = 0; mt < 4; mt++)
#pragma unroll
        for (int nt = 0; nt < 4; nt++) {
            int col = n0 + wn * 32 + nt * 8 + 2 * t4;
            float b0 = g_b2[col], b1 = g_b2[col + 1];
            int r = m0 + wm * 64 + mt * 16 + g8;
            *(float2*)&out[(size_t)r * DIM + col] =
                make_float2(acc[mt][nt][0] + b0, acc[mt][nt][1] + b1);
            *(float2*)&out[(size_t)(r + 8) * DIM + col] =
                make_float2(acc[mt][nt][2] + b0, acc[mt][nt][3] + b1);
        }
}

// ---------------------------------------------------------------------------
// Small precompute kernels: W2 = Wout(.,h-block) @ Wm, bias2 = b_out + Wout b_merge~
// ---------------------------------------------------------------------------
__global__ __launch_bounds__(256) void k_w2(const float* __restrict__ w_merge,
                                            const float* __restrict__ w_out) {
    int idx = blockIdx.x * 256 + threadIdx.x;
    int c = idx >> 9, i = idx & 511;
    int h = i >> 6, d = i & 63;
    const float* wo = w_out + (size_t)c * INNER + h * 64;
    float s = 0.f;
#pragma unroll 8
    for (int dp = 0; dp < 64; dp++) s += wo[dp] * w_merge[dp * 64 + d];
    g_w2[idx] = s;
}

__global__ void k_bias2(const float* __restrict__ w_out,
                        const float* __restrict__ b_merge,
                        const float* __restrict__ b_out) {
    int c = blockIdx.x * 256 + threadIdx.x;
    if (c < DIM) {
        float s = b_out[c];
        for (int i = 0; i < INNER; i++)
            s += w_out[(size_t)c * INNER + i] * b_merge[i & 63];
        g_b2[c] = s;
    }
}

__global__ __launch_bounds__(256) void k_copy(const float* __restrict__ src,
                                              float* __restrict__ dst, int n4) {
    int i = blockIdx.x * blockDim.x + threadIdx.x;
    if (i < n4) ((float4*)dst)[i] = ((const float4*)src)[i];
}

extern "C" void kernel_launch(void* const* d_in, const int* in_sizes, int n_in,
                              void* d_out, int out_size) {
    const float* x       = (const float*)d_in[0];
    const float* lidar   = (const float*)d_in[1];
    const float* w_qkv   = (const float*)d_in[2];
    const float* w_merge = (const float*)d_in[3];
    const float* b_merge = (const float*)d_in[4];
    const float* w_out   = (const float*)d_in[5];
    const float* b_out   = (const float*)d_in[6];
    const float* conv_w  = (const float*)d_in[7];
    float* out = (float*)d_out;

    k_qkv<<<dim3(12, 64), 256>>>(x, w_qkv);
    k_lstats<<<dim3(8, G), 256>>>(lidar);
    k_w2<<<1024, 256>>>(w_merge, w_out);
    k_bias2<<<2, 256>>>(w_out, b_merge, b_out);
    k_mid<<<dim3(8, 8, G), 256>>>(lidar, conv_w);
    k_midstats<<<G * N_, 256>>>();
    k_pv<<<dim3(8, G), 256>>>();
    k_out<<<dim3(4, 64), 256>>>(out);

    const int outElems = B_ * N_ * DIM;
    if (out_size >= 2 * outElems)
        k_copy<<<(outElems / 4 + 255) / 256, 256>>>(lidar, out + outElems,
                                                    outElems / 4);
}

// round 4
// speedup vs baseline: 2.7471x; 1.2967x over previous
#include <cuda_runtime.h>

namespace {
constexpr int B_ = 8, N_ = 1024, DIM = 512, H_ = 8, DH = 64, INNER = 512, G = 64;
constexpr float SCALE = 0.125f;
}

// Scratch (device globals — allocation-free rule)
__device__ float g_q[(size_t)G * N_ * DH];
__device__ float g_k[(size_t)G * N_ * DH];
__device__ float g_v[(size_t)G * N_ * DH];
__device__ float g_y[(size_t)B_ * N_ * INNER];
__device__ float g_ml[G * N_];
__device__ float g_isl[G * N_];
__device__ float g_w2[DIM * INNER];
__device__ float g_b2[DIM];

// ---------------------------------------------------------------------------
// tf32 helpers
// ---------------------------------------------------------------------------
__device__ __forceinline__ float cvt_tf32f(float x) {
    unsigned r;
    asm("cvt.rna.tf32.f32 %0, %1;" : "=r"(r) : "f"(x));
    return __uint_as_float(r);
}

__device__ __forceinline__ void mma8(float* d, const unsigned* a, const unsigned* b) {
    asm("mma.sync.aligned.m16n8k8.row.col.f32.tf32.tf32.f32 "
        "{%0,%1,%2,%3}, {%4,%5,%6,%7}, {%8,%9}, {%0,%1,%2,%3};"
        : "+f"(d[0]), "+f"(d[1]), "+f"(d[2]), "+f"(d[3])
        : "r"(a[0]), "r"(a[1]), "r"(a[2]), "r"(a[3]), "r"(b[0]), "r"(b[1]));
}

// One BK=32 slab of mma over smem tiles.
// A: [BM][ASTR] row-major along K.  B: n-major [BN][BSTR] (BKMAJ=false)
// or k-major [32][BSTR] (BKMAJ=true).
template <int MT, int NT, int WARPS_N, bool BKMAJ, int ASTR, int BSTR>
__device__ __forceinline__ void mma_slab(const float* As, const float* Bs,
                                         int warp, int g8, int t4,
                                         float (&acc)[MT][NT][4]) {
    const int wm = warp / WARPS_N, wn = warp % WARPS_N;
#pragma unroll
    for (int ks = 0; ks < 4; ks++) {
        const int c = ks * 8 + t4;
        unsigned af[MT][4], bf[NT][2];
#pragma unroll
        for (int mt = 0; mt < MT; mt++) {
            int r = wm * (MT * 16) + mt * 16 + g8;
            af[mt][0] = __float_as_uint(As[r * ASTR + c]);
            af[mt][1] = __float_as_uint(As[(r + 8) * ASTR + c]);
            af[mt][2] = __float_as_uint(As[r * ASTR + c + 4]);
            af[mt][3] = __float_as_uint(As[(r + 8) * ASTR + c + 4]);
        }
#pragma unroll
        for (int nt = 0; nt < NT; nt++) {
            int n = wn * (NT * 8) + nt * 8 + g8;
            if constexpr (BKMAJ) {
                bf[nt][0] = __float_as_uint(Bs[c * BSTR + n]);
                bf[nt][1] = __float_as_uint(Bs[(c + 4) * BSTR + n]);
            } else {
                bf[nt][0] = __float_as_uint(Bs[n * BSTR + c]);
                bf[nt][1] = __float_as_uint(Bs[n * BSTR + c + 4]);
            }
        }
#pragma unroll
        for (int mt = 0; mt < MT; mt++)
#pragma unroll
            for (int nt = 0; nt < NT; nt++)
                mma8(acc[mt][nt], af[mt], bf[nt]);
    }
}

// 128 rows x 32 cols gmem -> smem (stride 36), tf32-converted, optional scale.
__device__ __forceinline__ void load_tile_128x32(float* S, const float* gsrc,
                                                 int ldg, float scale) {
    const int t = threadIdx.x;
    const int r = t >> 3, c4 = (t & 7) * 4;
#pragma unroll
    for (int p = 0; p < 4; p++) {
        float4 v = *(const float4*)(gsrc + (size_t)(r + p * 32) * ldg + c4);
        float4 o;
        o.x = cvt_tf32f(v.x * scale);
        o.y = cvt_tf32f(v.y * scale);
        o.z = cvt_tf32f(v.z * scale);
        o.w = cvt_tf32f(v.w * scale);
        *(float4*)(S + (r + p * 32) * 36 + c4) = o;
    }
}

// ---------------------------------------------------------------------------
// K1: qkv = x @ w_qkv^T  (M=8192, N=1536, K=512) -> head-major q/k/v
// ---------------------------------------------------------------------------
__global__ __launch_bounds__(256) void k_qkv(const float* __restrict__ x,
                                             const float* __restrict__ w) {
    __shared__ float As[128 * 36], Bs[128 * 36];
    const int t = threadIdx.x, warp = t >> 5, lane = t & 31;
    const int g8 = lane >> 2, t4 = lane & 3;
    const int n0 = blockIdx.x * 128, m0 = blockIdx.y * 128;
    float acc[4][4][4] = {};
    for (int k0 = 0; k0 < DIM; k0 += 32) {
        __syncthreads();
        load_tile_128x32(As, x + (size_t)m0 * DIM + k0, DIM, 1.f);
        load_tile_128x32(Bs, w + (size_t)n0 * DIM + k0, DIM, 1.f);
        __syncthreads();
        mma_slab<4, 4, 4, false, 36, 36>(As, Bs, warp, g8, t4, acc);
    }
    const int wm = warp >> 2, wn = warp & 3;
#pragma unroll
    for (int mt = 0; mt < 4; mt++)
#pragma unroll
        for (int nt = 0; nt < 4; nt++) {
            int col = n0 + wn * 32 + nt * 8 + 2 * t4;
            int part = col >> 9, h = (col >> 6) & 7, d = col & 63;
            float* dst = part == 0 ? g_q : (part == 1 ? g_k : g_v);
#pragma unroll
            for (int half = 0; half < 2; half++) {
                int row = m0 + wm * 64 + mt * 16 + g8 + half * 8;
                int b = row >> 10, n = row & 1023;
                float2 val = half ? make_float2(acc[mt][nt][2], acc[mt][nt][3])
                                  : make_float2(acc[mt][nt][0], acc[mt][nt][1]);
                *(float2*)&dst[((size_t)((b * 8 + h) * 1024 + n)) * 64 + d] = val;
            }
        }
}

// ---------------------------------------------------------------------------
// K2: lidar softmax row stats (online, nothing materialized).
// ---------------------------------------------------------------------------
__global__ __launch_bounds__(256) void k_lstats(const float* __restrict__ lidar) {
    __shared__ float As[128 * 36], Bs[128 * 36];
    __shared__ float red[4][128], bcast[128], mrun[128], srun[128];
    const int t = threadIdx.x, warp = t >> 5, lane = t & 31;
    const int g8 = lane >> 2, t4 = lane & 3;
    const int gidx = blockIdx.y, b = gidx >> 3, h = gidx & 7;
    const int i0 = blockIdx.x * 128;
    const float* base = lidar + (size_t)b * N_ * INNER + h * 64;
    const int wm = warp >> 2, wn = warp & 3;
    if (t < 128) { mrun[t] = -1e30f; srun[t] = 0.f; }
    for (int jt = 0; jt < 8; jt++) {
        float acc[4][4][4] = {};
#pragma unroll
        for (int k0 = 0; k0 < 64; k0 += 32) {
            __syncthreads();
            load_tile_128x32(As, base + (size_t)i0 * INNER + k0, INNER, SCALE);
            load_tile_128x32(Bs, base + (size_t)(jt * 128) * INNER + k0, INNER, 1.f);
            __syncthreads();
            mma_slab<4, 4, 4, false, 36, 36>(As, Bs, warp, g8, t4, acc);
        }
        float vm[4][2];
#pragma unroll
        for (int mt = 0; mt < 4; mt++) {
            float a0 = -1e30f, a1 = -1e30f;
#pragma unroll
            for (int nt = 0; nt < 4; nt++) {
                a0 = fmaxf(a0, fmaxf(acc[mt][nt][0], acc[mt][nt][1]));
                a1 = fmaxf(a1, fmaxf(acc[mt][nt][2], acc[mt][nt][3]));
            }
#pragma unroll
            for (int off = 1; off <= 2; off <<= 1) {
                a0 = fmaxf(a0, __shfl_xor_sync(~0u, a0, off));
                a1 = fmaxf(a1, __shfl_xor_sync(~0u, a1, off));
            }
            vm[mt][0] = a0; vm[mt][1] = a1;
        }
        if (t4 == 0)
#pragma unroll
            for (int mt = 0; mt < 4; mt++) {
                red[wn][wm * 64 + mt * 16 + g8] = vm[mt][0];
                red[wn][wm * 64 + mt * 16 + g8 + 8] = vm[mt][1];
            }
        __syncthreads();
        if (t < 128) {
            float tm = fmaxf(fmaxf(red[0][t], red[1][t]), fmaxf(red[2][t], red[3][t]));
            bcast[t] = fmaxf(mrun[t], tm);
        }
        __syncthreads();
        float vs[4][2];
#pragma unroll
        for (int mt = 0; mt < 4; mt++) {
            int r = wm * 64 + mt * 16 + g8;
            float mn0 = bcast[r], mn1 = bcast[r + 8];
            float s0 = 0.f, s1 = 0.f;
#pragma unroll
            for (int nt = 0; nt < 4; nt++) {
                s0 += __expf(acc[mt][nt][0] - mn0) + __expf(acc[mt][nt][1] - mn0);
                s1 += __expf(acc[mt][nt][2] - mn1) + __expf(acc[mt][nt][3] - mn1);
            }
#pragma unroll
            for (int off = 1; off <= 2; off <<= 1) {
                s0 += __shfl_xor_sync(~0u, s0, off);
                s1 += __shfl_xor_sync(~0u, s1, off);
            }
            vs[mt][0] = s0; vs[mt][1] = s1;
        }
        __syncthreads();
        if (t4 == 0)
#pragma unroll
            for (int mt = 0; mt < 4; mt++) {
                red[wn][wm * 64 + mt * 16 + g8] = vs[mt][0];
                red[wn][wm * 64 + mt * 16 + g8 + 8] = vs[mt][1];
            }
        __syncthreads();
        if (t < 128) {
            float ts = red[0][t] + red[1][t] + red[2][t] + red[3][t];
            float mn = bcast[t];
            srun[t] = srun[t] * __expf(mrun[t] - mn) + ts;
            mrun[t] = mn;
        }
    }
    __syncthreads();
    if (t < 128) {
        g_ml[gidx * N_ + i0 + t] = mrun[t];
        g_isl[gidx * N_ + i0 + t] = 1.0f / srun[t];
    }
}

// ---------------------------------------------------------------------------
// K3 (flash): for each (g, i-tile of 128): loop j-tiles of 128:
//   mid_tile = c0*SCALE*qk + c1*lidar_softmax_tile (stats from k_lstats)
//   online softmax over j; O += P @ V with rescale. Writes O/l to g_y.
// Dynamic smem: Ps[128*132] aliases As/Bs; Vs[128*72]; stats.
// ---------------------------------------------------------------------------
__global__ __launch_bounds__(256, 1) void k_flash(const float* __restrict__ lidar,
                                                  const float* __restrict__ conv_w) {
    extern __shared__ float sm[];
    float* As = sm;                       // 128*36
    float* Bs = sm + 128 * 36;            // 128*36
    float* Ps = sm;                       // 128*132 (aliases As+Bs)
    float* Vs = sm + 128 * 132;           // 128*72
    float* mls = Vs + 128 * 72;
    float* isls = mls + 128;
    float* m_s = isls + 128;
    float* l_s = m_s + 128;
    float* al_s = l_s + 128;
    float* red = al_s + 128;              // 4*128

    const int t = threadIdx.x, warp = t >> 5, lane = t & 31;
    const int g8 = lane >> 2, t4 = lane & 3;
    const int gidx = blockIdx.y, i0 = blockIdx.x * 128;
    const int b = gidx >> 3, h = gidx & 7;
    const float c0 = conv_w[0], c1 = conv_w[1];
    const int wm = warp >> 2, wn = warp & 3;    // score layout (2x4 warps)
    const int wm2 = warp >> 1, wn2 = warp & 1;  // pv layout (4x2 warps)

    if (t < 128) {
        mls[t] = g_ml[gidx * N_ + i0 + t];
        isls[t] = g_isl[gidx * N_ + i0 + t];
        m_s[t] = -1e30f;
        l_s[t] = 0.f;
    }
    const float* lbase = lidar + (size_t)b * N_ * INNER + h * 64;
    const float* qb = g_q + (size_t)gidx * N_ * DH;
    const float* kb = g_k + (size_t)gidx * N_ * DH;
    const float* vb = g_v + (size_t)gidx * N_ * DH;

    float acc_o[2][4][4] = {};

    for (int j0 = 0; j0 < N_; j0 += 128) {
        float acc[4][4][4] = {};
        // --- lidar sim tile ---
#pragma unroll
        for (int k0 = 0; k0 < 64; k0 += 32) {
            __syncthreads();
            load_tile_128x32(As, lbase + (size_t)i0 * INNER + k0, INNER, SCALE);
            load_tile_128x32(Bs, lbase + (size_t)j0 * INNER + k0, INNER, 1.f);
            __syncthreads();
            mma_slab<4, 4, 4, false, 36, 36>(As, Bs, warp, g8, t4, acc);
        }
        // lidar softmax transform (row-wise, stats precomputed)
#pragma unroll
        for (int mt = 0; mt < 4; mt++) {
            int r = wm * 64 + mt * 16 + g8;
            float m0v = mls[r], i0v = isls[r] * c1;
            float m1v = mls[r + 8], i1v = isls[r + 8] * c1;
#pragma unroll
            for (int nt = 0; nt < 4; nt++) {
                acc[mt][nt][0] = i0v * __expf(acc[mt][nt][0] - m0v);
                acc[mt][nt][1] = i0v * __expf(acc[mt][nt][1] - m0v);
                acc[mt][nt][2] = i1v * __expf(acc[mt][nt][2] - m1v);
                acc[mt][nt][3] = i1v * __expf(acc[mt][nt][3] - m1v);
            }
        }
        // --- qk tile accumulate ---
#pragma unroll
        for (int k0 = 0; k0 < 64; k0 += 32) {
            __syncthreads();
            load_tile_128x32(As, qb + (size_t)i0 * DH + k0, DH, c0 * SCALE);
            load_tile_128x32(Bs, kb + (size_t)j0 * DH + k0, DH, 1.f);
            __syncthreads();
            mma_slab<4, 4, 4, false, 36, 36>(As, Bs, warp, g8, t4, acc);
        }
        // --- row max ---
        float vm[4][2];
#pragma unroll
        for (int mt = 0; mt < 4; mt++) {
            float a0 = -1e30f, a1 = -1e30f;
#pragma unroll
            for (int nt = 0; nt < 4; nt++) {
                a0 = fmaxf(a0, fmaxf(acc[mt][nt][0], acc[mt][nt][1]));
                a1 = fmaxf(a1, fmaxf(acc[mt][nt][2], acc[mt][nt][3]));
            }
#pragma unroll
            for (int off = 1; off <= 2; off <<= 1) {
                a0 = fmaxf(a0, __shfl_xor_sync(~0u, a0, off));
                a1 = fmaxf(a1, __shfl_xor_sync(~0u, a1, off));
            }
            vm[mt][0] = a0; vm[mt][1] = a1;
        }
        if (t4 == 0)
#pragma unroll
            for (int mt = 0; mt < 4; mt++) {
                red[wn * 128 + wm * 64 + mt * 16 + g8] = vm[mt][0];
                red[wn * 128 + wm * 64 + mt * 16 + g8 + 8] = vm[mt][1];
            }
        __syncthreads();
        if (t < 128) {
            float tm = fmaxf(fmaxf(red[t], red[128 + t]),
                             fmaxf(red[256 + t], red[384 + t]));
            float mo = m_s[t];
            float mn = fmaxf(mo, tm);
            al_s[t] = __expf(mo - mn);
            m_s[t] = mn;
        }
        __syncthreads();
        // --- p = exp(mid - m_new), row sums, write P to smem (tf32) ---
        float vs[4][2];
#pragma unroll
        for (int mt = 0; mt < 4; mt++) {
            int r = wm * 64 + mt * 16 + g8;
            float mn0 = m_s[r], mn1 = m_s[r + 8];
            float s0 = 0.f, s1 = 0.f;
#pragma unroll
            for (int nt = 0; nt < 4; nt++) {
                float p0 = __expf(acc[mt][nt][0] - mn0);
                float p1 = __expf(acc[mt][nt][1] - mn0);
                float p2 = __expf(acc[mt][nt][2] - mn1);
                float p3 = __expf(acc[mt][nt][3] - mn1);
                s0 += p0 + p1; s1 += p2 + p3;
                int cc = wn * 32 + nt * 8 + 2 * t4;
                *(float2*)&Ps[r * 132 + cc] =
                    make_float2(cvt_tf32f(p0), cvt_tf32f(p1));
                *(float2*)&Ps[(r + 8) * 132 + cc] =
                    make_float2(cvt_tf32f(p2), cvt_tf32f(p3));
            }
#pragma unroll
            for (int off = 1; off <= 2; off <<= 1) {
                s0 += __shfl_xor_sync(~0u, s0, off);
                s1 += __shfl_xor_sync(~0u, s1, off);
            }
            vs[mt][0] = s0; vs[mt][1] = s1;
        }
        if (t4 == 0)
#pragma unroll
            for (int mt = 0; mt < 4; mt++) {
                red[wn * 128 + wm * 64 + mt * 16 + g8] = vs[mt][0];
                red[wn * 128 + wm * 64 + mt * 16 + g8 + 8] = vs[mt][1];
            }
        // --- load V j-tile (no dependence on reductions) ---
        {
            int j = t >> 2, d16 = (t & 3) * 16;
#pragma unroll
            for (int p = 0; p < 2; p++) {
                int jj = j + p * 64;
                const float* src = vb + (size_t)(j0 + jj) * DH + d16;
#pragma unroll
                for (int q = 0; q < 4; q++) {
                    float4 v = *(const float4*)(src + q * 4);
                    float4 o;
                    o.x = cvt_tf32f(v.x); o.y = cvt_tf32f(v.y);
                    o.z = cvt_tf32f(v.z); o.w = cvt_tf32f(v.w);
                    *(float4*)(Vs + jj * 72 + d16 + q * 4) = o;
                }
            }
        }
        __syncthreads();
        if (t < 128)
            l_s[t] = l_s[t] * al_s[t] +
                     (red[t] + red[128 + t] + red[256 + t] + red[384 + t]);
        // rescale O accumulator by alpha (pv layout rows)
#pragma unroll
        for (int mt = 0; mt < 2; mt++) {
            int r = wm2 * 32 + mt * 16 + g8;
            float a0 = al_s[r], a1 = al_s[r + 8];
#pragma unroll
            for (int nt = 0; nt < 4; nt++) {
                acc_o[mt][nt][0] *= a0; acc_o[mt][nt][1] *= a0;
                acc_o[mt][nt][2] *= a1; acc_o[mt][nt][3] *= a1;
            }
        }
        // --- O += P @ V (K=128 in 4 slabs) ---
#pragma unroll
        for (int slab = 0; slab < 4; slab++)
            mma_slab<2, 4, 2, true, 132, 72>(Ps + slab * 32, Vs + (size_t)slab * 32 * 72,
                                             warp, g8, t4, acc_o);
    }
    __syncthreads();
    // epilogue: normalize and write to y[b, n, h*64 + d]
    float* yb = g_y + (size_t)b * N_ * INNER + h * 64;
#pragma unroll
    for (int mt = 0; mt < 2; mt++) {
        int r = wm2 * 32 + mt * 16 + g8;
        float inv0 = 1.0f / l_s[r], inv1 = 1.0f / l_s[r + 8];
#pragma unroll
        for (int nt = 0; nt < 4; nt++) {
            int d = wn2 * 32 + nt * 8 + 2 * t4;
            int n = i0 + r;
            *(float2*)&yb[(size_t)n * INNER + d] =
                make_float2(acc_o[mt][nt][0] * inv0, acc_o[mt][nt][1] * inv0);
            *(float2*)&yb[(size_t)(n + 8) * INNER + d] =
                make_float2(acc_o[mt][nt][2] * inv1, acc_o[mt][nt][3] * inv1);
        }
    }
}

// ---------------------------------------------------------------------------
// K4: out = y @ W2^T + bias2   (merge folded into W2)
// ---------------------------------------------------------------------------
__global__ __launch_bounds__(256) void k_out(float* __restrict__ out) {
    __shared__ float As[128 * 36], Bs[128 * 36];
    const int t = threadIdx.x, warp = t >> 5, lane = t & 31;
    const int g8 = lane >> 2, t4 = lane & 3;
    const int n0 = blockIdx.x * 128, m0 = blockIdx.y * 128;
    float acc[4][4][4] = {};
    for (int k0 = 0; k0 < INNER; k0 += 32) {
        __syncthreads();
        load_tile_128x32(As, g_y + (size_t)m0 * INNER + k0, INNER, 1.f);
        load_tile_128x32(Bs, g_w2 + (size_t)n0 * INNER + k0, INNER, 1.f);
        __syncthreads();
        mma_slab<4, 4, 4, false, 36, 36>(As, Bs, warp, g8, t4, acc);
    }
    const int wm = warp >> 2, wn = warp & 3;
#pragma unroll
    for (int mt = 0; mt < 4; mt++)
#pragma unroll
        for (int nt = 0; nt < 4; nt++) {
            int col = n0 + wn * 32 + nt * 8 + 2 * t4;
            float b0 = g_b2[col], b1 = g_b2[col + 1];
            int r = m0 + wm * 64 + mt * 16 + g8;
            *(float2*)&out[(size_t)r * DIM + col] =
                make_float2(acc[mt][nt][0] + b0, acc[mt][nt][1] + b1);
            *(float2*)&out[(size_t)(r + 8) * DIM + col] =
                make_float2(acc[mt][nt][2] + b0, acc[mt][nt][3] + b1);
        }
}

// ---------------------------------------------------------------------------
// Precompute: W2 = Wout(.,h-block) @ Wm ; bias2 = b_out + Wout b_merge~
// ---------------------------------------------------------------------------
__global__ __launch_bounds__(256) void k_w2(const float* __restrict__ w_merge,
                                            const float* __restrict__ w_out) {
    int idx = blockIdx.x * 256 + threadIdx.x;
    int c = idx >> 9, i = idx & 511;
    int h = i >> 6, d = i & 63;
    const float* wo = w_out + (size_t)c * INNER + h * 64;
    float s = 0.f;
#pragma unroll 8
    for (int dp = 0; dp < 64; dp++) s += wo[dp] * w_merge[dp * 64 + d];
    g_w2[idx] = s;
}

__global__ __launch_bounds__(256) void k_bias2(const float* __restrict__ w_out,
                                               const float* __restrict__ b_merge,
                                               const float* __restrict__ b_out) {
    int c = blockIdx.x * 8 + (threadIdx.x >> 5);
    int lane = threadIdx.x & 31;
    float s = 0.f;
    for (int i = lane; i < INNER; i += 32)
        s += w_out[(size_t)c * INNER + i] * b_merge[i & 63];
    for (int o = 16; o; o >>= 1) s += __shfl_xor_sync(~0u, s, o);
    if (lane == 0) g_b2[c] = b_out[c] + s;
}

__global__ __launch_bounds__(256) void k_copy(const float* __restrict__ src,
                                              float* __restrict__ dst, int n4) {
    int i = blockIdx.x * blockDim.x + threadIdx.x;
    if (i < n4) ((float4*)dst)[i] = ((const float4*)src)[i];
}

extern "C" void kernel_launch(void* const* d_in, const int* in_sizes, int n_in,
                              void* d_out, int out_size) {
    const float* x       = (const float*)d_in[0];
    const float* lidar   = (const float*)d_in[1];
    const float* w_qkv   = (const float*)d_in[2];
    const float* w_merge = (const float*)d_in[3];
    const float* b_merge = (const float*)d_in[4];
    const float* w_out   = (const float*)d_in[5];
    const float* b_out   = (const float*)d_in[6];
    const float* conv_w  = (const float*)d_in[7];
    float* out = (float*)d_out;

    // dynamic smem for k_flash: (128*132 + 128*72 + 9*128) floats
    const int flashSmem = (128 * 132 + 128 * 72 + 9 * 128) * 4;
    cudaFuncSetAttribute(k_flash, cudaFuncAttributeMaxDynamicSharedMemorySize,
                         flashSmem);

    k_qkv<<<dim3(12, 64), 256>>>(x, w_qkv);
    k_lstats<<<dim3(8, G), 256>>>(lidar);
    k_w2<<<1024, 256>>>(w_merge, w_out);
    k_bias2<<<64, 256>>>(w_out, b_merge, b_out);
    k_flash<<<dim3(8, G), 256, flashSmem>>>(lidar, conv_w);
    k_out<<<dim3(4, 64), 256>>>(out);

    const int outElems = B_ * N_ * DIM;
    if (out_size >= 2 * outElems)
        k_copy<<<(outElems / 4 + 255) / 256, 256>>>(lidar, out + outElems,
                                                    outElems / 4);
}